// round 9
// baseline (speedup 1.0000x reference)
#include <cuda_runtime.h>
#include <math.h>

// Problem constants (fixed by reference setup)
#define N_NODES   7400000      // 200000 * 37
#define NPG       37

// Scratch accumulator: sum of edge messages into each node.
// PRECONDITION: all-zero before each kernel_launch call. Holds initially
// (BSS zero-init at module load) and is re-established by graph_kernel,
// which zeroes its own slice after consuming it.
__device__ float g_agg[N_NODES];

// ---------------------------------------------------------------------------
// Kernel 1: per-edge MLP + scatter-add, 4 edges/thread (proven-best config).
// ew(a) = b2 + sum_j relu(a*W1j+b1j)*W2j ; msg = x[src]*ew ; RED into g_agg.
// ---------------------------------------------------------------------------
#define EPT 4
__global__ void __launch_bounds__(256) edge_kernel(
                            const float* __restrict__ ea,
                            const int*   __restrict__ src,
                            const int*   __restrict__ dst,
                            const float* __restrict__ x,
                            const float* __restrict__ W1,
                            const float* __restrict__ b1,
                            const float* __restrict__ W2,
                            const float* __restrict__ b2,
                            int E)
{
    int i = blockIdx.x * blockDim.x + threadIdx.x;
    int base = i * EPT;
    if (base >= E) return;

    float w1[4], c1[4], w2[4];
#pragma unroll
    for (int j = 0; j < 4; j++) { w1[j] = W1[j]; c1[j] = b1[j]; w2[j] = W2[j]; }
    float c2 = b2[0];

    if (base + EPT - 1 < E) {
        float4 a = *reinterpret_cast<const float4*>(ea + base);
        int4   s = *reinterpret_cast<const int4*>(src + base);
        int4   d = *reinterpret_cast<const int4*>(dst + base);
        float av[4] = {a.x, a.y, a.z, a.w};
        int   sv[4] = {s.x, s.y, s.z, s.w};
        int   dv[4] = {d.x, d.y, d.z, d.w};

        float ew[4];
#pragma unroll
        for (int e = 0; e < 4; e++) {
            float acc = c2;
#pragma unroll
            for (int j = 0; j < 4; j++)
                acc = fmaf(fmaxf(fmaf(av[e], w1[j], c1[j]), 0.0f), w2[j], acc);
            ew[e] = acc;
        }
#pragma unroll
        for (int e = 0; e < 4; e++) {
            float msg = __ldg(x + sv[e]) * ew[e];
            atomicAdd(&g_agg[dv[e]], msg);
        }
    } else {
        for (int k = base; k < E; k++) {
            float a = ea[k];
            float acc = c2;
#pragma unroll
            for (int j = 0; j < 4; j++)
                acc = fmaf(fmaxf(fmaf(a, w1[j], c1[j]), 0.0f), w2[j], acc);
            float msg = __ldg(x + src[k]) * acc;
            atomicAdd(&g_agg[dst[k]], msg);
        }
    }
}

// ---------------------------------------------------------------------------
// Kernel 2: per-graph MLP (37->8->8->2) + angle epilogue.
// Fuses the node update v = agg + x*root + conv_bias into the smem staging
// pass, and re-zeroes this block's g_agg slice for the next replay.
// NOTE: sg must be 16B-aligned for the float4 (STS.128) staging path.
// ---------------------------------------------------------------------------
#define GPB 128
__global__ void graph_kernel(const float* __restrict__ x,
                             const float* __restrict__ root,
                             const float* __restrict__ conv_bias,
                             const float* __restrict__ Wa,
                             const float* __restrict__ ba,
                             const float* __restrict__ Wb,
                             const float* __restrict__ bb,
                             const float* __restrict__ Wc,
                             const float* __restrict__ bc,
                             float* __restrict__ out,
                             int n_graphs)
{
    __shared__ __align__(16) float sg[GPB * NPG];
    __shared__ __align__(16) float sW[400];   // 394 used, padded to 16B multiple

    int tid = threadIdx.x;
    for (int i = tid; i < 394; i += GPB) {
        float v;
        if      (i < 296) v = Wa[i];
        else if (i < 304) v = ba[i - 296];
        else if (i < 368) v = Wb[i - 304];
        else if (i < 376) v = bb[i - 368];
        else if (i < 392) v = Wc[i - 376];
        else              v = bc[i - 392];
        sW[i] = v;
    }

    float r  = root[0];
    float cb = conv_bias[0];

    int gbase = blockIdx.x * GPB;
    int ngb = n_graphs - gbase;
    if (ngb > GPB) ngb = GPB;
    int nload = ngb * NPG;

    float*       aggp = g_agg + (size_t)gbase * NPG;   // 16B aligned: 128*37*4 = 18944 | 16
    const float* xp   = x     + (size_t)gbase * NPG;

    // Vectorized stage: v = agg + x*r + cb into smem; zero agg slice behind us.
    int n4 = nload >> 2;                 // float4 count
    const float4* ap4 = reinterpret_cast<const float4*>(aggp);
    const float4* xp4 = reinterpret_cast<const float4*>(xp);
    float4*       aw4 = reinterpret_cast<float4*>(aggp);
    float4*       sg4 = reinterpret_cast<float4*>(sg);
    const float4  z4  = make_float4(0.f, 0.f, 0.f, 0.f);
    for (int i = tid; i < n4; i += GPB) {
        float4 av = ap4[i];
        float4 xv = xp4[i];
        float4 o;
        o.x = fmaf(xv.x, r, av.x + cb);
        o.y = fmaf(xv.y, r, av.y + cb);
        o.z = fmaf(xv.z, r, av.z + cb);
        o.w = fmaf(xv.w, r, av.w + cb);
        sg4[i] = o;
        aw4[i] = z4;                     // re-zero for next replay
    }
    for (int i = (n4 << 2) + tid; i < nload; i += GPB) {
        float av = aggp[i];
        sg[i] = fmaf(xp[i], r, av + cb);
        aggp[i] = 0.0f;
    }
    __syncthreads();

    int g = gbase + tid;
    if (tid >= ngb || g >= n_graphs) return;

    const float* v = sg + tid * NPG;
    const float* sWa = sW;
    const float* sba = sW + 296;
    const float* sWb = sW + 304;
    const float* sbb = sW + 368;
    const float* sWc = sW + 376;
    const float* sbc = sW + 392;

    float h1[8];
#pragma unroll
    for (int j = 0; j < 8; j++) h1[j] = sba[j];
    for (int k = 0; k < NPG; k++) {
        float vk = v[k];
#pragma unroll
        for (int j = 0; j < 8; j++) h1[j] = fmaf(vk, sWa[k * 8 + j], h1[j]);
    }
#pragma unroll
    for (int j = 0; j < 8; j++) h1[j] = fmaxf(h1[j], 0.0f);

    float h2[8];
#pragma unroll
    for (int j = 0; j < 8; j++) h2[j] = sbb[j];
#pragma unroll
    for (int k = 0; k < 8; k++) {
#pragma unroll
        for (int j = 0; j < 8; j++) h2[j] = fmaf(h1[k], sWb[k * 8 + j], h2[j]);
    }
#pragma unroll
    for (int j = 0; j < 8; j++) h2[j] = fmaxf(h2[j], 0.0f);

    float X = sbc[0], Y = sbc[1];
#pragma unroll
    for (int k = 0; k < 8; k++) {
        X = fmaf(h2[k], sWc[k * 2 + 0], X);
        Y = fmaf(h2[k], sWc[k * 2 + 1], Y);
    }

    float sgn = (Y > 0.0f) ? 1.0f : ((Y < 0.0f) ? -1.0f : 0.0f);
    float angle = atanf(X / Y) + 1.5707963267948966f * sgn + 3.141592653589793f;
    out[g] = angle * 1.909859317102744f;   // 12 / (2*pi)
}

// ---------------------------------------------------------------------------
extern "C" void kernel_launch(void* const* d_in, const int* in_sizes, int n_in,
                              void* d_out, int out_size)
{
    const float* x         = (const float*)d_in[0];
    const float* edge_attr = (const float*)d_in[1];
    const float* W1        = (const float*)d_in[2];
    const float* b1        = (const float*)d_in[3];
    const float* W2        = (const float*)d_in[4];
    const float* b2        = (const float*)d_in[5];
    const float* root      = (const float*)d_in[6];
    const float* conv_bias = (const float*)d_in[7];
    const float* Wa        = (const float*)d_in[8];
    const float* ba        = (const float*)d_in[9];
    const float* Wb        = (const float*)d_in[10];
    const float* bb        = (const float*)d_in[11];
    const float* Wc        = (const float*)d_in[12];
    const float* bc        = (const float*)d_in[13];
    const int*   edge_index= (const int*)d_in[14];

    int N = in_sizes[0];      // node count (x is (N,1))
    int E = in_sizes[1];      // edge count (edge_attr is (E,1))
    int n_graphs = N / NPG;

    const int* src = edge_index;
    const int* dst = edge_index + E;

    float* out = (float*)d_out;

    {
        int threads = 256;
        int work = (E + EPT - 1) / EPT;
        int blocks = (work + threads - 1) / threads;
        edge_kernel<<<blocks, threads>>>(edge_attr, src, dst, x,
                                         W1, b1, W2, b2, E);
    }
    {
        int blocks = (n_graphs + GPB - 1) / GPB;
        graph_kernel<<<blocks, GPB>>>(x, root, conv_bias,
                                      Wa, ba, Wb, bb, Wc, bc, out, n_graphs);
    }
}

// round 10
// speedup vs baseline: 1.0089x; 1.0089x over previous
#include <cuda_runtime.h>
#include <math.h>

// Problem constants (fixed by reference setup)
#define N_NODES   7400000      // 200000 * 37
#define NPG       37

// Scratch accumulator: zeroed by a memset node at the start of every launch.
__device__ float g_agg[N_NODES];

// ---------------------------------------------------------------------------
// Kernel 1: per-edge MLP + scatter-add, 4 edges/thread (proven-best config).
// ew(a) = b2 + sum_j relu(a*W1j+b1j)*W2j ; msg = x[src]*ew ; RED into g_agg.
// ---------------------------------------------------------------------------
#define EPT 4
__global__ void __launch_bounds__(256) edge_kernel(
                            const float* __restrict__ ea,
                            const int*   __restrict__ src,
                            const int*   __restrict__ dst,
                            const float* __restrict__ x,
                            const float* __restrict__ W1,
                            const float* __restrict__ b1,
                            const float* __restrict__ W2,
                            const float* __restrict__ b2,
                            int E)
{
    int i = blockIdx.x * blockDim.x + threadIdx.x;
    int base = i * EPT;
    if (base >= E) return;

    float w1[4], c1[4], w2[4];
#pragma unroll
    for (int j = 0; j < 4; j++) { w1[j] = W1[j]; c1[j] = b1[j]; w2[j] = W2[j]; }
    float c2 = b2[0];

    if (base + EPT - 1 < E) {
        float4 a = *reinterpret_cast<const float4*>(ea + base);
        int4   s = *reinterpret_cast<const int4*>(src + base);
        int4   d = *reinterpret_cast<const int4*>(dst + base);
        float av[4] = {a.x, a.y, a.z, a.w};
        int   sv[4] = {s.x, s.y, s.z, s.w};
        int   dv[4] = {d.x, d.y, d.z, d.w};

        float ew[4];
#pragma unroll
        for (int e = 0; e < 4; e++) {
            float acc = c2;
#pragma unroll
            for (int j = 0; j < 4; j++)
                acc = fmaf(fmaxf(fmaf(av[e], w1[j], c1[j]), 0.0f), w2[j], acc);
            ew[e] = acc;
        }
#pragma unroll
        for (int e = 0; e < 4; e++) {
            float msg = __ldg(x + sv[e]) * ew[e];
            atomicAdd(&g_agg[dv[e]], msg);
        }
    } else {
        for (int k = base; k < E; k++) {
            float a = ea[k];
            float acc = c2;
#pragma unroll
            for (int j = 0; j < 4; j++)
                acc = fmaf(fmaxf(fmaf(a, w1[j], c1[j]), 0.0f), w2[j], acc);
            float msg = __ldg(x + src[k]) * acc;
            atomicAdd(&g_agg[dst[k]], msg);
        }
    }
}

// ---------------------------------------------------------------------------
// Kernel 2: per-graph MLP (37->8->8->2) + angle epilogue.
// Read-only fused staging: v = agg + x*root + conv_bias (no writes to g_agg —
// zeroing is a separate memset node). 256 threads = 256 graphs per block.
// ---------------------------------------------------------------------------
#define GPB 256
__global__ void __launch_bounds__(GPB) graph_kernel(
                             const float* __restrict__ x,
                             const float* __restrict__ root,
                             const float* __restrict__ conv_bias,
                             const float* __restrict__ Wa,
                             const float* __restrict__ ba,
                             const float* __restrict__ Wb,
                             const float* __restrict__ bb,
                             const float* __restrict__ Wc,
                             const float* __restrict__ bc,
                             float* __restrict__ out,
                             int n_graphs)
{
    __shared__ __align__(16) float sg[GPB * NPG];   // 256*37 floats = 37888 B
    __shared__ __align__(16) float sW[400];         // 394 used

    int tid = threadIdx.x;
    for (int i = tid; i < 394; i += GPB) {
        float v;
        if      (i < 296) v = Wa[i];
        else if (i < 304) v = ba[i - 296];
        else if (i < 368) v = Wb[i - 304];
        else if (i < 376) v = bb[i - 368];
        else if (i < 392) v = Wc[i - 376];
        else              v = bc[i - 392];
        sW[i] = v;
    }

    float r  = root[0];
    float cb = conv_bias[0];

    int gbase = blockIdx.x * GPB;
    int ngb = n_graphs - gbase;
    if (ngb > GPB) ngb = GPB;
    int nload = ngb * NPG;

    const float* aggp = g_agg + (size_t)gbase * NPG;  // 256*37*4=37888 B steps: 16B-aligned
    const float* xp   = x     + (size_t)gbase * NPG;

    // Read-only vectorized stage: v = agg + x*r + cb into smem.
    int n4 = nload >> 2;
    const float4* ap4 = reinterpret_cast<const float4*>(aggp);
    const float4* xp4 = reinterpret_cast<const float4*>(xp);
    float4*       sg4 = reinterpret_cast<float4*>(sg);
    for (int i = tid; i < n4; i += GPB) {
        float4 av = ap4[i];
        float4 xv = xp4[i];
        float4 o;
        o.x = fmaf(xv.x, r, av.x + cb);
        o.y = fmaf(xv.y, r, av.y + cb);
        o.z = fmaf(xv.z, r, av.z + cb);
        o.w = fmaf(xv.w, r, av.w + cb);
        sg4[i] = o;
    }
    for (int i = (n4 << 2) + tid; i < nload; i += GPB)
        sg[i] = fmaf(xp[i], r, aggp[i] + cb);
    __syncthreads();

    int g = gbase + tid;
    if (tid >= ngb || g >= n_graphs) return;

    const float* v = sg + tid * NPG;
    const float* sWa = sW;
    const float* sba = sW + 296;
    const float* sWb = sW + 304;
    const float* sbb = sW + 368;
    const float* sWc = sW + 376;
    const float* sbc = sW + 392;

    float h1[8];
#pragma unroll
    for (int j = 0; j < 8; j++) h1[j] = sba[j];
    for (int k = 0; k < NPG; k++) {
        float vk = v[k];
#pragma unroll
        for (int j = 0; j < 8; j++) h1[j] = fmaf(vk, sWa[k * 8 + j], h1[j]);
    }
#pragma unroll
    for (int j = 0; j < 8; j++) h1[j] = fmaxf(h1[j], 0.0f);

    float h2[8];
#pragma unroll
    for (int j = 0; j < 8; j++) h2[j] = sbb[j];
#pragma unroll
    for (int k = 0; k < 8; k++) {
#pragma unroll
        for (int j = 0; j < 8; j++) h2[j] = fmaf(h1[k], sWb[k * 8 + j], h2[j]);
    }
#pragma unroll
    for (int j = 0; j < 8; j++) h2[j] = fmaxf(h2[j], 0.0f);

    float X = sbc[0], Y = sbc[1];
#pragma unroll
    for (int k = 0; k < 8; k++) {
        X = fmaf(h2[k], sWc[k * 2 + 0], X);
        Y = fmaf(h2[k], sWc[k * 2 + 1], Y);
    }

    float sgn = (Y > 0.0f) ? 1.0f : ((Y < 0.0f) ? -1.0f : 0.0f);
    float angle = atanf(X / Y) + 1.5707963267948966f * sgn + 3.141592653589793f;
    out[g] = angle * 1.909859317102744f;   // 12 / (2*pi)
}

// ---------------------------------------------------------------------------
extern "C" void kernel_launch(void* const* d_in, const int* in_sizes, int n_in,
                              void* d_out, int out_size)
{
    const float* x         = (const float*)d_in[0];
    const float* edge_attr = (const float*)d_in[1];
    const float* W1        = (const float*)d_in[2];
    const float* b1        = (const float*)d_in[3];
    const float* W2        = (const float*)d_in[4];
    const float* b2        = (const float*)d_in[5];
    const float* root      = (const float*)d_in[6];
    const float* conv_bias = (const float*)d_in[7];
    const float* Wa        = (const float*)d_in[8];
    const float* ba        = (const float*)d_in[9];
    const float* Wb        = (const float*)d_in[10];
    const float* bb        = (const float*)d_in[11];
    const float* Wc        = (const float*)d_in[12];
    const float* bc        = (const float*)d_in[13];
    const int*   edge_index= (const int*)d_in[14];

    int N = in_sizes[0];      // node count (x is (N,1))
    int E = in_sizes[1];      // edge count (edge_attr is (E,1))
    int n_graphs = N / NPG;

    const int* src = edge_index;
    const int* dst = edge_index + E;

    float* out = (float*)d_out;

    // Zero accumulator with a memset node (≈4 µs at full write BW; runs in
    // every launch, so no cross-call precondition is needed).
    void* agg_ptr = nullptr;
    cudaGetSymbolAddress(&agg_ptr, g_agg);
    cudaMemsetAsync(agg_ptr, 0, (size_t)N * sizeof(float));

    {
        int threads = 256;
        int work = (E + EPT - 1) / EPT;
        int blocks = (work + threads - 1) / threads;
        edge_kernel<<<blocks, threads>>>(edge_attr, src, dst, x,
                                         W1, b1, W2, b2, E);
    }
    {
        int blocks = (n_graphs + GPB - 1) / GPB;
        graph_kernel<<<blocks, GPB>>>(x, root, conv_bias,
                                      Wa, ba, Wb, bb, Wc, bc, out, n_graphs);
    }
}

// round 12
// speedup vs baseline: 1.0121x; 1.0032x over previous
#include <cuda_runtime.h>
#include <math.h>

// Problem constants (fixed by reference setup)
#define N_NODES   7400000      // 200000 * 37
#define NPG       37

// Scratch accumulator: zeroed by a memset node at the start of every launch.
__device__ float g_agg[N_NODES];

// ---------------------------------------------------------------------------
// Kernel 1: per-edge MLP + scatter-add, 4 edges/thread.
// Streamed inputs (ea/src/dst) use __ldcs (evict-first) so the hot 60MB
// (x + g_agg) stays L2-resident; REDs then RMW in L2 instead of DRAM.
// Gathers stay __ldg (L1-cached) — R6 proved L1 on gathers is critical.
// ---------------------------------------------------------------------------
#define EPT 4
__global__ void __launch_bounds__(256) edge_kernel(
                            const float* __restrict__ ea,
                            const int*   __restrict__ src,
                            const int*   __restrict__ dst,
                            const float* __restrict__ x,
                            const float* __restrict__ W1,
                            const float* __restrict__ b1,
                            const float* __restrict__ W2,
                            const float* __restrict__ b2,
                            int E)
{
    int i = blockIdx.x * blockDim.x + threadIdx.x;
    int base = i * EPT;
    if (base >= E) return;

    float w1[4], c1[4], w2[4];
#pragma unroll
    for (int j = 0; j < 4; j++) { w1[j] = W1[j]; c1[j] = b1[j]; w2[j] = W2[j]; }
    float c2 = b2[0];

    if (base + EPT - 1 < E) {
        float4 a = __ldcs(reinterpret_cast<const float4*>(ea + base));
        int4   s = __ldcs(reinterpret_cast<const int4*>(src + base));
        int4   d = __ldcs(reinterpret_cast<const int4*>(dst + base));
        float av[4] = {a.x, a.y, a.z, a.w};
        int   sv[4] = {s.x, s.y, s.z, s.w};
        int   dv[4] = {d.x, d.y, d.z, d.w};

        float ew[4];
#pragma unroll
        for (int e = 0; e < 4; e++) {
            float acc = c2;
#pragma unroll
            for (int j = 0; j < 4; j++)
                acc = fmaf(fmaxf(fmaf(av[e], w1[j], c1[j]), 0.0f), w2[j], acc);
            ew[e] = acc;
        }
#pragma unroll
        for (int e = 0; e < 4; e++) {
            float msg = __ldg(x + sv[e]) * ew[e];
            atomicAdd(&g_agg[dv[e]], msg);
        }
    } else {
        for (int k = base; k < E; k++) {
            float a = __ldcs(ea + k);
            float acc = c2;
#pragma unroll
            for (int j = 0; j < 4; j++)
                acc = fmaf(fmaxf(fmaf(a, w1[j], c1[j]), 0.0f), w2[j], acc);
            float msg = __ldg(x + __ldcs(src + k)) * acc;
            atomicAdd(&g_agg[__ldcs(dst + k)], msg);
        }
    }
}

// ---------------------------------------------------------------------------
// Kernel 2: per-graph MLP (37->8->8->2) + angle epilogue.
// Read-only fused staging: v = agg + x*root + conv_bias (no writes to g_agg —
// zeroing is a separate memset node). 256 threads = 256 graphs per block.
// ---------------------------------------------------------------------------
#define GPB 256
__global__ void __launch_bounds__(GPB) graph_kernel(
                             const float* __restrict__ x,
                             const float* __restrict__ root,
                             const float* __restrict__ conv_bias,
                             const float* __restrict__ Wa,
                             const float* __restrict__ ba,
                             const float* __restrict__ Wb,
                             const float* __restrict__ bb,
                             const float* __restrict__ Wc,
                             const float* __restrict__ bc,
                             float* __restrict__ out,
                             int n_graphs)
{
    __shared__ __align__(16) float sg[GPB * NPG];   // 256*37 floats = 37888 B
    __shared__ __align__(16) float sW[400];         // 394 used

    int tid = threadIdx.x;
    for (int i = tid; i < 394; i += GPB) {
        float v;
        if      (i < 296) v = Wa[i];
        else if (i < 304) v = ba[i - 296];
        else if (i < 368) v = Wb[i - 304];
        else if (i < 376) v = bb[i - 368];
        else if (i < 392) v = Wc[i - 376];
        else              v = bc[i - 392];
        sW[i] = v;
    }

    float r  = root[0];
    float cb = conv_bias[0];

    int gbase = blockIdx.x * GPB;
    int ngb = n_graphs - gbase;
    if (ngb > GPB) ngb = GPB;
    int nload = ngb * NPG;

    const float* aggp = g_agg + (size_t)gbase * NPG;  // 256*37*4=37888 B steps: 16B-aligned
    const float* xp   = x     + (size_t)gbase * NPG;

    // Read-only vectorized stage: v = agg + x*r + cb into smem.
    int n4 = nload >> 2;
    const float4* ap4 = reinterpret_cast<const float4*>(aggp);
    const float4* xp4 = reinterpret_cast<const float4*>(xp);
    float4*       sg4 = reinterpret_cast<float4*>(sg);
    for (int i = tid; i < n4; i += GPB) {
        float4 av = ap4[i];
        float4 xv = xp4[i];
        float4 o;
        o.x = fmaf(xv.x, r, av.x + cb);
        o.y = fmaf(xv.y, r, av.y + cb);
        o.z = fmaf(xv.z, r, av.z + cb);
        o.w = fmaf(xv.w, r, av.w + cb);
        sg4[i] = o;
    }
    for (int i = (n4 << 2) + tid; i < nload; i += GPB)
        sg[i] = fmaf(xp[i], r, aggp[i] + cb);
    __syncthreads();

    int g = gbase + tid;
    if (tid >= ngb || g >= n_graphs) return;

    const float* v = sg + tid * NPG;
    const float* sWa = sW;
    const float* sba = sW + 296;
    const float* sWb = sW + 304;
    const float* sbb = sW + 368;
    const float* sWc = sW + 376;
    const float* sbc = sW + 392;

    float h1[8];
#pragma unroll
    for (int j = 0; j < 8; j++) h1[j] = sba[j];
    for (int k = 0; k < NPG; k++) {
        float vk = v[k];
#pragma unroll
        for (int j = 0; j < 8; j++) h1[j] = fmaf(vk, sWa[k * 8 + j], h1[j]);
    }
#pragma unroll
    for (int j = 0; j < 8; j++) h1[j] = fmaxf(h1[j], 0.0f);

    float h2[8];
#pragma unroll
    for (int j = 0; j < 8; j++) h2[j] = sbb[j];
#pragma unroll
    for (int k = 0; k < 8; k++) {
#pragma unroll
        for (int j = 0; j < 8; j++) h2[j] = fmaf(h1[k], sWb[k * 8 + j], h2[j]);
    }
#pragma unroll
    for (int j = 0; j < 8; j++) h2[j] = fmaxf(h2[j], 0.0f);

    float X = sbc[0], Y = sbc[1];
#pragma unroll
    for (int k = 0; k < 8; k++) {
        X = fmaf(h2[k], sWc[k * 2 + 0], X);
        Y = fmaf(h2[k], sWc[k * 2 + 1], Y);
    }

    float sgn = (Y > 0.0f) ? 1.0f : ((Y < 0.0f) ? -1.0f : 0.0f);
    float angle = atanf(X / Y) + 1.5707963267948966f * sgn + 3.141592653589793f;
    out[g] = angle * 1.909859317102744f;   // 12 / (2*pi)
}

// ---------------------------------------------------------------------------
extern "C" void kernel_launch(void* const* d_in, const int* in_sizes, int n_in,
                              void* d_out, int out_size)
{
    const float* x         = (const float*)d_in[0];
    const float* edge_attr = (const float*)d_in[1];
    const float* W1        = (const float*)d_in[2];
    const float* b1        = (const float*)d_in[3];
    const float* W2        = (const float*)d_in[4];
    const float* b2        = (const float*)d_in[5];
    const float* root      = (const float*)d_in[6];
    const float* conv_bias = (const float*)d_in[7];
    const float* Wa        = (const float*)d_in[8];
    const float* ba        = (const float*)d_in[9];
    const float* Wb        = (const float*)d_in[10];
    const float* bb        = (const float*)d_in[11];
    const float* Wc        = (const float*)d_in[12];
    const float* bc        = (const float*)d_in[13];
    const int*   edge_index= (const int*)d_in[14];

    int N = in_sizes[0];      // node count (x is (N,1))
    int E = in_sizes[1];      // edge count (edge_attr is (E,1))
    int n_graphs = N / NPG;

    const int* src = edge_index;
    const int* dst = edge_index + E;

    float* out = (float*)d_out;

    // Zero accumulator with a memset node (≈4 µs at full write BW; runs in
    // every launch, so no cross-call precondition is needed).
    void* agg_ptr = nullptr;
    cudaGetSymbolAddress(&agg_ptr, g_agg);
    cudaMemsetAsync(agg_ptr, 0, (size_t)N * sizeof(float));

    {
        int threads = 256;
        int work = (E + EPT - 1) / EPT;
        int blocks = (work + threads - 1) / threads;
        edge_kernel<<<blocks, threads>>>(edge_attr, src, dst, x,
                                         W1, b1, W2, b2, E);
    }
    {
        int blocks = (n_graphs + GPB - 1) / GPB;
        graph_kernel<<<blocks, GPB>>>(x, root, conv_bias,
                                      Wa, ba, Wb, bb, Wc, bc, out, n_graphs);
    }
}

// round 13
// speedup vs baseline: 1.0152x; 1.0031x over previous
#include <cuda_runtime.h>
#include <math.h>

// Problem constants (fixed by reference setup)
#define N_NODES   7400000      // 200000 * 37
#define NPG       37

// Scratch accumulator: zeroed by a memset node at the start of every launch.
__device__ float g_agg[N_NODES];

// ---------------------------------------------------------------------------
// Kernel 1: per-edge MLP + scatter-add, 4 edges/thread.  (CONVERGED — at the
// L1TEX wavefront floor: ~1 gather wavefront + ~1.29 cyc REDG per edge.)
// ---------------------------------------------------------------------------
#define EPT 4
__global__ void __launch_bounds__(256) edge_kernel(
                            const float* __restrict__ ea,
                            const int*   __restrict__ src,
                            const int*   __restrict__ dst,
                            const float* __restrict__ x,
                            const float* __restrict__ W1,
                            const float* __restrict__ b1,
                            const float* __restrict__ W2,
                            const float* __restrict__ b2,
                            int E)
{
    int i = blockIdx.x * blockDim.x + threadIdx.x;
    int base = i * EPT;
    if (base >= E) return;

    float w1[4], c1[4], w2[4];
#pragma unroll
    for (int j = 0; j < 4; j++) { w1[j] = W1[j]; c1[j] = b1[j]; w2[j] = W2[j]; }
    float c2 = b2[0];

    if (base + EPT - 1 < E) {
        float4 a = __ldcs(reinterpret_cast<const float4*>(ea + base));
        int4   s = __ldcs(reinterpret_cast<const int4*>(src + base));
        int4   d = __ldcs(reinterpret_cast<const int4*>(dst + base));
        float av[4] = {a.x, a.y, a.z, a.w};
        int   sv[4] = {s.x, s.y, s.z, s.w};
        int   dv[4] = {d.x, d.y, d.z, d.w};

        float ew[4];
#pragma unroll
        for (int e = 0; e < 4; e++) {
            float acc = c2;
#pragma unroll
            for (int j = 0; j < 4; j++)
                acc = fmaf(fmaxf(fmaf(av[e], w1[j], c1[j]), 0.0f), w2[j], acc);
            ew[e] = acc;
        }
#pragma unroll
        for (int e = 0; e < 4; e++) {
            float msg = __ldg(x + sv[e]) * ew[e];
            atomicAdd(&g_agg[dv[e]], msg);
        }
    } else {
        for (int k = base; k < E; k++) {
            float a = __ldcs(ea + k);
            float acc = c2;
#pragma unroll
            for (int j = 0; j < 4; j++)
                acc = fmaf(fmaxf(fmaf(a, w1[j], c1[j]), 0.0f), w2[j], acc);
            float msg = __ldg(x + __ldcs(src + k)) * acc;
            atomicAdd(&g_agg[__ldcs(dst + k)], msg);
        }
    }
}

// ---------------------------------------------------------------------------
// Kernel 2: per-graph MLP (37->8->8->2) + angle epilogue.
// Staging is latency-bound -> force high occupancy (8 blocks/SM, <=32 regs),
// evict-first loads on the read-once streams, 2-deep ILP in the stage loop.
// ---------------------------------------------------------------------------
#define GPB 256
__global__ void __launch_bounds__(GPB, 8) graph_kernel(
                             const float* __restrict__ x,
                             const float* __restrict__ root,
                             const float* __restrict__ conv_bias,
                             const float* __restrict__ Wa,
                             const float* __restrict__ ba,
                             const float* __restrict__ Wb,
                             const float* __restrict__ bb,
                             const float* __restrict__ Wc,
                             const float* __restrict__ bc,
                             float* __restrict__ out,
                             int n_graphs)
{
    __shared__ __align__(16) float sg[GPB * NPG];   // 256*37 floats = 37888 B
    __shared__ __align__(16) float sW[400];         // 394 used

    int tid = threadIdx.x;
    for (int i = tid; i < 394; i += GPB) {
        float v;
        if      (i < 296) v = Wa[i];
        else if (i < 304) v = ba[i - 296];
        else if (i < 368) v = Wb[i - 304];
        else if (i < 376) v = bb[i - 368];
        else if (i < 392) v = Wc[i - 376];
        else              v = bc[i - 392];
        sW[i] = v;
    }

    float r  = root[0];
    float cb = conv_bias[0];

    int gbase = blockIdx.x * GPB;
    int ngb = n_graphs - gbase;
    if (ngb > GPB) ngb = GPB;
    int nload = ngb * NPG;

    const float* aggp = g_agg + (size_t)gbase * NPG;  // 37888 B steps: 16B-aligned
    const float* xp   = x     + (size_t)gbase * NPG;

    // Read-once vectorized stage: v = agg + x*r + cb into smem (2-deep ILP).
    int n4 = nload >> 2;
    const float4* ap4 = reinterpret_cast<const float4*>(aggp);
    const float4* xp4 = reinterpret_cast<const float4*>(xp);
    float4*       sg4 = reinterpret_cast<float4*>(sg);
    int i = tid;
    for (; i + GPB < n4; i += 2 * GPB) {
        float4 av0 = __ldcs(ap4 + i);
        float4 xv0 = __ldcs(xp4 + i);
        float4 av1 = __ldcs(ap4 + i + GPB);
        float4 xv1 = __ldcs(xp4 + i + GPB);
        float4 o0, o1;
        o0.x = fmaf(xv0.x, r, av0.x + cb);
        o0.y = fmaf(xv0.y, r, av0.y + cb);
        o0.z = fmaf(xv0.z, r, av0.z + cb);
        o0.w = fmaf(xv0.w, r, av0.w + cb);
        o1.x = fmaf(xv1.x, r, av1.x + cb);
        o1.y = fmaf(xv1.y, r, av1.y + cb);
        o1.z = fmaf(xv1.z, r, av1.z + cb);
        o1.w = fmaf(xv1.w, r, av1.w + cb);
        sg4[i] = o0;
        sg4[i + GPB] = o1;
    }
    for (; i < n4; i += GPB) {
        float4 av = __ldcs(ap4 + i);
        float4 xv = __ldcs(xp4 + i);
        float4 o;
        o.x = fmaf(xv.x, r, av.x + cb);
        o.y = fmaf(xv.y, r, av.y + cb);
        o.z = fmaf(xv.z, r, av.z + cb);
        o.w = fmaf(xv.w, r, av.w + cb);
        sg4[i] = o;
    }
    for (int j = (n4 << 2) + tid; j < nload; j += GPB)
        sg[j] = fmaf(xp[j], r, aggp[j] + cb);
    __syncthreads();

    int g = gbase + tid;
    if (tid >= ngb || g >= n_graphs) return;

    const float* v = sg + tid * NPG;
    const float* sWa = sW;
    const float* sba = sW + 296;
    const float* sWb = sW + 304;
    const float* sbb = sW + 368;
    const float* sWc = sW + 376;
    const float* sbc = sW + 392;

    float h1[8];
#pragma unroll
    for (int j = 0; j < 8; j++) h1[j] = sba[j];
    for (int k = 0; k < NPG; k++) {
        float vk = v[k];
#pragma unroll
        for (int j = 0; j < 8; j++) h1[j] = fmaf(vk, sWa[k * 8 + j], h1[j]);
    }
#pragma unroll
    for (int j = 0; j < 8; j++) h1[j] = fmaxf(h1[j], 0.0f);

    float h2[8];
#pragma unroll
    for (int j = 0; j < 8; j++) h2[j] = sbb[j];
#pragma unroll
    for (int k = 0; k < 8; k++) {
#pragma unroll
        for (int j = 0; j < 8; j++) h2[j] = fmaf(h1[k], sWb[k * 8 + j], h2[j]);
    }
#pragma unroll
    for (int j = 0; j < 8; j++) h2[j] = fmaxf(h2[j], 0.0f);

    float X = sbc[0], Y = sbc[1];
#pragma unroll
    for (int k = 0; k < 8; k++) {
        X = fmaf(h2[k], sWc[k * 2 + 0], X);
        Y = fmaf(h2[k], sWc[k * 2 + 1], Y);
    }

    float sgn = (Y > 0.0f) ? 1.0f : ((Y < 0.0f) ? -1.0f : 0.0f);
    float angle = atanf(X / Y) + 1.5707963267948966f * sgn + 3.141592653589793f;
    out[g] = angle * 1.909859317102744f;   // 12 / (2*pi)
}

// ---------------------------------------------------------------------------
extern "C" void kernel_launch(void* const* d_in, const int* in_sizes, int n_in,
                              void* d_out, int out_size)
{
    const float* x         = (const float*)d_in[0];
    const float* edge_attr = (const float*)d_in[1];
    const float* W1        = (const float*)d_in[2];
    const float* b1        = (const float*)d_in[3];
    const float* W2        = (const float*)d_in[4];
    const float* b2        = (const float*)d_in[5];
    const float* root      = (const float*)d_in[6];
    const float* conv_bias = (const float*)d_in[7];
    const float* Wa        = (const float*)d_in[8];
    const float* ba        = (const float*)d_in[9];
    const float* Wb        = (const float*)d_in[10];
    const float* bb        = (const float*)d_in[11];
    const float* Wc        = (const float*)d_in[12];
    const float* bc        = (const float*)d_in[13];
    const int*   edge_index= (const int*)d_in[14];

    int N = in_sizes[0];      // node count (x is (N,1))
    int E = in_sizes[1];      // edge count (edge_attr is (E,1))
    int n_graphs = N / NPG;

    const int* src = edge_index;
    const int* dst = edge_index + E;

    float* out = (float*)d_out;

    // Zero accumulator with a memset node.
    void* agg_ptr = nullptr;
    cudaGetSymbolAddress(&agg_ptr, g_agg);
    cudaMemsetAsync(agg_ptr, 0, (size_t)N * sizeof(float));

    {
        int threads = 256;
        int work = (E + EPT - 1) / EPT;
        int blocks = (work + threads - 1) / threads;
        edge_kernel<<<blocks, threads>>>(edge_attr, src, dst, x,
                                         W1, b1, W2, b2, E);
    }
    {
        int blocks = (n_graphs + GPB - 1) / GPB;
        graph_kernel<<<blocks, GPB>>>(x, root, conv_bias,
                                      Wa, ba, Wb, bb, Wc, bc, out, n_graphs);
    }
}